// round 8
// baseline (speedup 1.0000x reference)
#include <cuda_runtime.h>
#include <cuda_bf16.h>
#include <math.h>
#include <stdint.h>

// Problem constants (fixed by dataset)
#define BB    8
#define NTOK  4096
#define DD    512
#define HH    64
#define LDS_  68        // padded row stride (floats) for 64x64 tile

#define TWO_PI 6.28318530717958647692f

// ---------------- scratch (static device globals; no allocation) -------------
__device__ float g_xt[BB * DD * NTOK];              // x transposed: [B][D][N]
__device__ __nv_bfloat16 g_combh[BB * 1024 * NTOK]; // hi(comb) [B][k][n]
__device__ __nv_bfloat16 g_combl[BB * 1024 * NTOK]; // lo(comb) [B][k][n]
__device__ __nv_bfloat16 g_Wh[DD * 1024];           // hi(Wout) [j][k]
__device__ __nv_bfloat16 g_Wl[DD * 1024];           // lo(Wout) [j][k]
__device__ float g_pooled[BB * DD];
__device__ float g_gamma[BB * DD];

// ---------------- small asm helpers ------------------------------------------
__device__ __forceinline__ uint32_t smem_u32(const void* p) {
    uint32_t a;
    asm("{.reg .u64 t; cvta.to.shared.u64 t, %1; cvt.u32.u64 %0, t;}" : "=r"(a) : "l"(p));
    return a;
}
__device__ __forceinline__ void ldmx4t(uint32_t* r, uint32_t a) {
    asm volatile("ldmatrix.sync.aligned.m8n8.x4.trans.shared.b16 {%0,%1,%2,%3}, [%4];"
                 : "=r"(r[0]), "=r"(r[1]), "=r"(r[2]), "=r"(r[3]) : "r"(a));
}
__device__ __forceinline__ void ldmx2(uint32_t* r, uint32_t a) {
    asm volatile("ldmatrix.sync.aligned.m8n8.x2.shared.b16 {%0,%1}, [%2];"
                 : "=r"(r[0]), "=r"(r[1]) : "r"(a));
}
__device__ __forceinline__ void mma16816(float* c, const uint32_t* a, const uint32_t* b) {
    asm volatile("mma.sync.aligned.m16n8k16.row.col.f32.bf16.bf16.f32 "
                 "{%0,%1,%2,%3}, {%4,%5,%6,%7}, {%8,%9}, {%0,%1,%2,%3};"
                 : "+f"(c[0]), "+f"(c[1]), "+f"(c[2]), "+f"(c[3])
                 : "r"(a[0]), "r"(a[1]), "r"(a[2]), "r"(a[3]), "r"(b[0]), "r"(b[1]));
}
__device__ __forceinline__ void cp16(uint32_t sdst, const void* gsrc) {
    asm volatile("cp.async.ca.shared.global [%0], [%1], 16;" :: "r"(sdst), "l"(gsrc));
}
__device__ __forceinline__ void cp_commit() {
    asm volatile("cp.async.commit_group;");
}
__device__ __forceinline__ void split_bf16(float v, __nv_bfloat16& h, __nv_bfloat16& l) {
    h = __float2bfloat16(v);
    l = __float2bfloat16(v - __bfloat162float(h));
}

// exact logistic reaction on one complex value (r,m) for time with exp term ex
__device__ __forceinline__ void react1(float& r, float& m,
                                       float a2, float b2, bool tiny,
                                       float tt, float ex) {
    float q = r * r + m * m;
    float qn;
    if (tiny) qn = q / (1.f + b2 * q * tt);
    else { float den = fmaxf(b2 * q + (a2 - b2 * q) * ex, 1e-8f); qn = a2 * q / den; }
    qn = fmaxf(qn, 0.f);
    float sc = sqrtf(qn / fmaxf(q, 1e-8f));
    r *= sc; m *= sc;
}

// ---------------- 8-point FFT (SGN=-1 fwd, +1 inv; unnormalized) -------------
template<int SGN>
__device__ __forceinline__ void fft8(float* xr, float* xi) {
    const float s = (float)SGN;
    float a0r = xr[0] + xr[4], a0i = xi[0] + xi[4];
    float a1r = xr[0] - xr[4], a1i = xi[0] - xi[4];
    float b0r = xr[2] + xr[6], b0i = xi[2] + xi[6];
    float b1r = xr[2] - xr[6], b1i = xi[2] - xi[6];
    float c0r = xr[1] + xr[5], c0i = xi[1] + xi[5];
    float c1r = xr[1] - xr[5], c1i = xi[1] - xi[5];
    float d0r = xr[3] + xr[7], d0i = xi[3] + xi[7];
    float d1r = xr[3] - xr[7], d1i = xi[3] - xi[7];
    float e0r = a0r + b0r, e0i = a0i + b0i;
    float e2r = a0r - b0r, e2i = a0i - b0i;
    float wbr = -s * b1i,  wbi =  s * b1r;
    float e1r = a1r + wbr, e1i = a1i + wbi;
    float e3r = a1r - wbr, e3i = a1i - wbi;
    float o0r = c0r + d0r, o0i = c0i + d0i;
    float o2r = c0r - d0r, o2i = c0i - d0i;
    float wdr = -s * d1i,  wdi =  s * d1r;
    float o1r = c1r + wdr, o1i = c1i + wdi;
    float o3r = c1r - wdr, o3i = c1i - wdi;
    const float r2 = 0.70710678118654752440f;
    float t1r =  r2 * (o1r - s * o1i), t1i = r2 * (o1i + s * o1r);
    float t2r = -s * o2i,              t2i = s * o2r;
    float t3r = -r2 * (o3r + s * o3i), t3i = r2 * (s * o3r - o3i);
    xr[0] = e0r + o0r; xi[0] = e0i + o0i;
    xr[4] = e0r - o0r; xi[4] = e0i - o0i;
    xr[1] = e1r + t1r; xi[1] = e1i + t1i;
    xr[5] = e1r - t1r; xi[5] = e1i - t1i;
    xr[2] = e2r + t2r; xi[2] = e2i + t2i;
    xr[6] = e2r - t2r; xi[6] = e2i - t2i;
    xr[3] = e3r + t3r; xi[3] = e3i + t3i;
    xr[7] = e3r - t3r; xi[7] = e3i - t3i;
}

// One 64-pt line: [optional reaction] -> fwd FFT -> x phase1d(k) (1/64 folded)
// -> inv FFT -> [optional reaction] -> store.
// 8 threads (t=0..7) per line; layout in/out: elem n at slot (t + 8j).
// Transposes through smem with XOR-swizzled slots: slot(a,b) = 8a + (a^b).
template<bool RLOAD, bool RSTORE>
__device__ __forceinline__ void do_line(
    float* sre, float* sim, int base, int stride, int t,
    const float* twr, const float* twi, const float* phr, const float* phi,
    float a2, float b2, bool tiny,
    float ttL, float exL, float ttS, float exS)
{
    float xr[8], xi[8];
#pragma unroll
    for (int j = 0; j < 8; j++) {
        int p = base + (t + 8 * j) * stride;
        xr[j] = sre[p]; xi[j] = sim[p];
        if (RLOAD) react1(xr[j], xi[j], a2, b2, tiny, ttL, exL);
    }
    fft8<-1>(xr, xi);                       // over n2 -> reg index k1
#pragma unroll
    for (int j = 1; j < 8; j++) {           // * W64^{t*k1}
        float r = xr[j] * twr[j] - xi[j] * twi[j];
        float m = xr[j] * twi[j] + xi[j] * twr[j];
        xr[j] = r; xi[j] = m;
    }
    __syncwarp();
#pragma unroll
    for (int j = 0; j < 8; j++) { int p = base + (8 * t + (t ^ j)) * stride; sre[p] = xr[j]; sim[p] = xi[j]; }
    __syncwarp();
#pragma unroll
    for (int j = 0; j < 8; j++) { int p = base + (8 * j + (t ^ j)) * stride; xr[j] = sre[p]; xi[j] = sim[p]; }
    fft8<-1>(xr, xi);                       // over n1 -> reg index k2; X[t + 8*k2]
#pragma unroll
    for (int j = 0; j < 8; j++) {           // * phase[k] * (1/64)
        int k = t + 8 * j;
        float pr = phr[k], pi = phi[k];
        float r = xr[j] * pr - xi[j] * pi;
        float m = xr[j] * pi + xi[j] * pr;
        xr[j] = r; xi[j] = m;
    }
    fft8<1>(xr, xi);                        // inverse over k2 -> reg index n1
#pragma unroll
    for (int j = 1; j < 8; j++) {           // * conj(W64^{t*n1})
        float r = xr[j] * twr[j] + xi[j] * twi[j];
        float m = xi[j] * twr[j] - xr[j] * twi[j];
        xr[j] = r; xi[j] = m;
    }
    __syncwarp();
#pragma unroll
    for (int j = 0; j < 8; j++) { int p = base + (8 * t + (t ^ j)) * stride; sre[p] = xr[j]; sim[p] = xi[j]; }
    __syncwarp();
#pragma unroll
    for (int j = 0; j < 8; j++) { int p = base + (8 * j + (t ^ j)) * stride; xr[j] = sre[p]; xi[j] = sim[p]; }
    fft8<1>(xr, xi);                        // inverse over k1 -> reg index n2
#pragma unroll
    for (int j = 0; j < 8; j++) {
        if (RSTORE) react1(xr[j], xi[j], a2, b2, tiny, ttS, exS);
        int p = base + (t + 8 * j) * stride;
        sre[p] = xr[j]; sim[p] = xi[j];
    }
}

// ---------------- kernels ----------------------------------------------------

__global__ void k_transpose_x(const float* __restrict__ x) {
    __shared__ float tile[32][33];
    int b = blockIdx.z;
    int d0 = blockIdx.x * 32, n0 = blockIdx.y * 32;
    int tx = threadIdx.x, ty = threadIdx.y;
#pragma unroll
    for (int i = 0; i < 32; i += 8)
        tile[ty + i][tx] = x[((size_t)b * NTOK + n0 + ty + i) * DD + d0 + tx];
    __syncthreads();
#pragma unroll
    for (int i = 0; i < 32; i += 8)
        g_xt[((size_t)b * DD + d0 + ty + i) * NTOK + n0 + tx] = tile[tx][ty + i];
}

// Wout is [j=512][k=1024] row-major already: elementwise hi/lo bf16 split.
__global__ void k_prep_w(const float* __restrict__ Wout) {
    int idx = blockIdx.x * 256 + threadIdx.x;
    float v = Wout[idx];
    __nv_bfloat16 h, l;
    split_bf16(v, h, l);
    g_Wh[idx] = h; g_Wl[idx] = l;
}

__global__ void k_pooled() {
    int g = blockIdx.x * 8 + (threadIdx.x >> 5);   // channel id b*512+d
    int lane = threadIdx.x & 31;
    const float* p = g_xt + (size_t)g * NTOK;
    float s = 0.f;
    for (int i = lane; i < NTOK; i += 32) s += p[i];
#pragma unroll
    for (int o = 16; o; o >>= 1) s += __shfl_down_sync(0xffffffffu, s, o);
    if (!lane) g_pooled[g] = s * (1.0f / NTOK);
}

__global__ void k_gamma(const float* __restrict__ Wg, const float* __restrict__ bg,
                        const float* __restrict__ log_base) {
    int g = blockIdx.x * 8 + (threadIdx.x >> 5);   // b*512+d
    int b = g >> 9, d = g & 511;
    int lane = threadIdx.x & 31;
    const float* pw = Wg + (size_t)d * DD;
    const float* pp = g_pooled + (size_t)b * DD;
    float s = 0.f;
    for (int k = lane; k < DD; k += 32) s += pp[k] * pw[k];
#pragma unroll
    for (int o = 16; o; o >>= 1) s += __shfl_down_sync(0xffffffffu, s, o);
    if (!lane) {
        float z = s + bg[d] + log_base[d];
        float sp = (z > 20.f) ? z : log1pf(expf(z));
        g_gamma[g] = fminf(sp, 0.35f);
    }
}

__global__ void __launch_bounds__(256) k_main(const float* __restrict__ alpha_raw,
                                              const float* __restrict__ beta_raw,
                                              const int* __restrict__ k_steps_p) {
    __shared__ float sre[HH * LDS_];
    __shared__ float sim[HH * LDS_];
    __shared__ float phr[64], phi[64];

    int bd  = blockIdx.x;
    int d   = bd & 511;
    int tid = threadIdx.x;
    int t   = tid & 7;
    int grp = tid >> 3;            // 0..31

    // x-pass line assignment: within a warp (groups 4w..4w+3, i = grp&3) use
    // lines spaced by 2 so row-base banks are 68*line = 8i + const (mod 32)
    // -> every x-direction smem round hits 32 distinct banks. Bijection over
    // 0..63: line = 2i + b + 8a (+32*rep), a = grp>>3, b = (grp>>2)&1.
    int xline0 = 2 * (grp & 3) + ((grp >> 2) & 1) + ((grp >> 3) << 3);

    int ks = *k_steps_p; if (ks < 1) ks = 1;
    float dt = 1.0f / (float)ks;

    float gamma = g_gamma[bd];
    float alpha = 0.25f * tanhf(alpha_raw[d]);
    float brw = beta_raw[d];
    float beta = ((brw > 20.f) ? brw : log1pf(expf(brw))) + 1e-4f;

    if (tid < 64) {
        float e = 2.0f * cosf((float)tid * (TWO_PI / 64.0f)) - 2.0f;
        float arg = dt * gamma * e;
        float sn, cs; sincosf(arg, &sn, &cs);
        phr[tid] = cs * (1.0f / 64.0f);   // 1/64 per dimension -> 1/4096 total
        phi[tid] = sn * (1.0f / 64.0f);
    }

    float twr[8], twi[8];
#pragma unroll
    for (int j = 0; j < 8; j++) {
        float ang = (float)(t * j) * (TWO_PI / 64.0f);
        float sn, cs; sincosf(ang, &sn, &cs);
        twr[j] = cs; twi[j] = -sn;        // forward W64^{t*j}; inverse = conj
    }

    const float* src = g_xt + (size_t)bd * NTOK;
    for (int i = tid; i < NTOK; i += 256) {
        int y = i >> 6, xx = i & 63;
        sre[y * LDS_ + xx] = src[i];
        sim[y * LDS_ + xx] = 0.f;
    }
    __syncthreads();

    // reaction time constants. Strang splitting R(th) D [R(tf) D]^(ks-1) R(th)
    // with exact-flow merge of interior half steps. Reactions are fused into
    // the FFT passes: x-pass applies R on load (th for step 0, tf after);
    // last step's y-pass applies the trailing R(th) on store.
    float a2 = 2.f * alpha, b2 = 2.f * beta;
    bool tiny = fabsf(a2) < 1e-6f;
    float th = 0.5f * dt, tf = dt;
    float exh = expf(-a2 * th), exf = expf(-a2 * tf);

    for (int step = 0; step < ks; ++step) {
        float ttL = (step == 0) ? th : tf;
        float exL = (step == 0) ? exh : exf;
        bool last = (step == ks - 1);
        // ---- x-direction (rows): reaction on load + diffusion
#pragma unroll
        for (int rep = 0; rep < 2; rep++) {
            int line = xline0 + 32 * rep;
            do_line<true, false>(sre, sim, line * LDS_, 1, t, twr, twi, phr, phi,
                                 a2, b2, tiny, ttL, exL, 0.f, 0.f);
        }
        __syncthreads();
        // ---- y-direction (columns); trailing half reaction on last step
        if (last) {
#pragma unroll
            for (int rep = 0; rep < 2; rep++) {
                int line = grp + 32 * rep;
                do_line<false, true>(sre, sim, line, LDS_, t, twr, twi, phr, phi,
                                     a2, b2, tiny, 0.f, 0.f, th, exh);
            }
        } else {
#pragma unroll
            for (int rep = 0; rep < 2; rep++) {
                int line = grp + 32 * rep;
                do_line<false, false>(sre, sim, line, LDS_, t, twr, twi, phr, phi,
                                      a2, b2, tiny, 0.f, 0.f, 0.f, 0.f);
            }
        }
        __syncthreads();
    }

    // epilogue: hi/lo bf16 split, [k][n] layout (coalesced along n)
    int b = bd >> 9;
    size_t baser = ((size_t)b * 1024 + d) * NTOK;
    size_t basei = ((size_t)b * 1024 + 512 + d) * NTOK;
    for (int i = tid; i < NTOK; i += 256) {
        int idx = (i >> 6) * LDS_ + (i & 63);
        __nv_bfloat16 h, l;
        split_bf16(sre[idx], h, l);
        g_combh[baser + i] = h; g_combl[baser + i] = l;
        split_bf16(sim[idx], h, l);
        g_combh[basei + i] = h; g_combl[basei + i] = l;
    }
}

// out[b,n,j] = sum_k comb[k,n]*W[j,k] + x[b,n,j]*Dp[j]
// bf16 tensor-core GEMM, hi/lo 3-term split, 2-stage cp.async pipeline.
// A is consumed DIRECTLY from comb's [k][n] layout via ldmatrix.trans
// (no pre-transpose kernel). Block: 128(n) x 128(j), K-step 16; 8 warps =
// 2(mw) x 4(jw), warp tile 64x32 via m16n8k16.
//
// A smem tile: [stage][buf][krow 0..15][n 0..127] bf16, row stride 272B
//   (68 words: 64 data + 4 pad). ldmatrix.trans: 8 addrs = 8 consecutive
//   k-rows, 16B of n each; banks (4r+c) mod 32 cover all 32 once.
// B (W) smem tile: [stage][buf][j 0..127][k 0..15] bf16, row stride 48B,
//   non-trans ldmatrix as before.
#define AROWW  68                         // A row stride in words (272B)
#define ABUFW  (16 * AROWW)               // 1088 words
#define ASTGW  (2 * ABUFW)                // 2176 words (8704B)
#define ROWW   12                         // B row stride in words (48B)
#define BUFW   (128 * ROWW)               // 1536 words
#define STGW   (2 * BUFW)                 // 3072 words (12288B)

__global__ void __launch_bounds__(256, 2) k_gemm(const float* __restrict__ x,
                                                 const float* __restrict__ Dp,
                                                 float* __restrict__ out) {
    __shared__ uint32_t Ash[2 * ASTGW];   // ~17.4KB
    __shared__ uint32_t Bsh[2 * STGW];    // 24KB  (total ~41.4KB)

    int b  = blockIdx.z;
    int j0 = blockIdx.x * 128;            // j fastest -> A-tile L2 reuse across 4 CTAs
    int m0 = blockIdx.y * 128;
    int tid = threadIdx.x;
    int warp = tid >> 5, lane = tid & 31;
    int mw = warp & 1, jw = warp >> 1;

    float acc[4][4][4];
#pragma unroll
    for (int ms = 0; ms < 4; ms++)
#pragma unroll
        for (int js = 0; js < 4; js++)
#pragma unroll
            for (int e = 0; e < 4; e++) acc[ms][js][e] = 0.f;

    uint32_t aBase = smem_u32(Ash);
    uint32_t bBase = smem_u32(Bsh);
    // A ldmatrix.trans per-lane address (frag order: {m0-7,k0-7},{m8-15,k0-7},
    // {m0-7,k8-15},{m8-15,k8-15}): lane group g=lane>>3 -> matrix g;
    // k-row = (g>>1)*8 + (lane&7); n-offset = (g&1)*8 elems.
    int matA = lane >> 3, rinA = lane & 7;
    uint32_t aAddr0 = aBase +
        (uint32_t)((((matA >> 1) * 8 + rinA) * AROWW + (matA & 1) * 4 + mw * 32) * 4);
    int l16 = lane & 15;
    int matB = l16 >> 3, rinB = l16 & 7;
    uint32_t bAddr0 = bBase + (uint32_t)(((jw * 32 + rinB) * ROWW + matB * 4) * 4);

    auto load_stage = [&](int st, int k0) {
        // A: 2 bufs x 16 k-rows x 16 chunks(16B) = 512 cp16
#pragma unroll
        for (int u = 0; u < 2; u++) {
            int idx = tid + 256 * u;
            int buf = idx >> 8, r = (idx >> 4) & 15, c = idx & 15;
            const __nv_bfloat16* As = buf ? g_combl : g_combh;
            const void* g = As + ((size_t)(b * 1024 + k0 + r)) * NTOK + m0 + c * 8;
            cp16(aBase + (uint32_t)((st * ASTGW + buf * ABUFW + r * AROWW + c * 4) * 4), g);
        }
        // B: 2 bufs x 128 j-rows x 2 chunks = 512 cp16
#pragma unroll
        for (int u = 0; u < 2; u++) {
            int idx = tid + 256 * u;
            int buf = idx >> 8, r = (idx >> 1) & 127, c = idx & 1;
            const __nv_bfloat16* Ws = buf ? g_Wl : g_Wh;
            const void* g = Ws + (size_t)(j0 + r) * 1024 + k0 + c * 8;
            cp16(bBase + (uint32_t)((st * STGW + buf * BUFW + r * ROWW + c * 4) * 4), g);
        }
        cp_commit();
    };

    load_stage(0, 0);

    for (int it = 0; it < 64; ++it) {
        int cur = it & 1;
        if (it + 1 < 64) {
            load_stage(cur ^ 1, (it + 1) * 16);
            asm volatile("cp.async.wait_group 1;" ::: "memory");
        } else {
            asm volatile("cp.async.wait_group 0;" ::: "memory");
        }
        __syncthreads();

        uint32_t aS = aAddr0 + (uint32_t)(cur * ASTGW * 4);
        uint32_t bS = bAddr0 + (uint32_t)(cur * STGW * 4);
        uint32_t bh[4][2], bl[4][2];
#pragma unroll
        for (int js = 0; js < 4; js++) {
            ldmx2(bh[js], bS + js * 8 * ROWW * 4);
            ldmx2(bl[js], bS + js * 8 * ROWW * 4 + BUFW * 4);
        }
#pragma unroll
        for (int ms = 0; ms < 4; ms++) {
            uint32_t ah[4], al[4];
            ldmx4t(ah, aS + ms * 32);                 // ms*16 n-elems = 8 words
            ldmx4t(al, aS + ms * 32 + ABUFW * 4);
#pragma unroll
            for (int js = 0; js < 4; js++) {
                mma16816(acc[ms][js], ah, bh[js]);
                mma16816(acc[ms][js], ah, bl[js]);
                mma16816(acc[ms][js], al, bh[js]);
            }
        }
        __syncthreads();
    }

    // epilogue: D frag: d0,d1 = (row l>>2, col (l&3)*2, +1); d2,d3 = row+8
    int rg = lane >> 2, cp = (lane & 3) * 2;
#pragma unroll
    for (int ms = 0; ms < 4; ms++) {
#pragma unroll
        for (int js = 0; js < 4; js++) {
            int j = j0 + jw * 32 + js * 8 + cp;
            float2 dpv = *(const float2*)(Dp + j);
            int n = m0 + mw * 64 + ms * 16 + rg;
            size_t idx0 = ((size_t)b * NTOK + n) * DD + j;
            float2 xv0 = *(const float2*)(x + idx0);
            float2 o0;
            o0.x = acc[ms][js][0] + xv0.x * dpv.x;
            o0.y = acc[ms][js][1] + xv0.y * dpv.y;
            *(float2*)(out + idx0) = o0;
            size_t idx1 = idx0 + 8 * DD;
            float2 xv1 = *(const float2*)(x + idx1);
            float2 o1;
            o1.x = acc[ms][js][2] + xv1.x * dpv.x;
            o1.y = acc[ms][js][3] + xv1.y * dpv.y;
            *(float2*)(out + idx1) = o1;
        }
    }
}

// ---------------- launch ------------------------------------------------------
extern "C" void kernel_launch(void* const* d_in, const int* in_sizes, int n_in,
                              void* d_out, int out_size) {
    const float* x         = (const float*)d_in[0];
    const float* Wg        = (const float*)d_in[1];
    const float* bg        = (const float*)d_in[2];
    const float* log_base  = (const float*)d_in[3];
    const float* alpha_raw = (const float*)d_in[4];
    const float* beta_raw  = (const float*)d_in[5];
    const float* Wout      = (const float*)d_in[6];
    const float* Dparam    = (const float*)d_in[7];
    const int*   k_steps   = (const int*)d_in[8];
    float* out = (float*)d_out;

    k_transpose_x<<<dim3(DD / 32, NTOK / 32, BB), dim3(32, 8)>>>(x);
    k_prep_w<<<(DD * 1024) / 256, 256>>>(Wout);
    k_pooled<<<BB * DD / 8, 256>>>();
    k_gamma<<<BB * DD / 8, 256>>>(Wg, bg, log_base);
    k_main<<<BB * DD, 256>>>(alpha_raw, beta_raw, k_steps);
    k_gemm<<<dim3(DD / 128, NTOK / 128, BB), 256>>>(x, Dparam, out);
}

// round 16
// speedup vs baseline: 1.2192x; 1.2192x over previous
#include <cuda_runtime.h>
#include <cuda_bf16.h>
#include <math.h>
#include <stdint.h>

// Problem constants (fixed by dataset)
#define BB    8
#define NTOK  4096
#define DD    512
#define HH    64
#define LDS_  68        // padded row stride (in float2 elems) for 64x64 tile

#define TWO_PI 6.28318530717958647692f

// ---------------- scratch (static device globals; no allocation) -------------
__device__ float g_xt[BB * DD * NTOK];              // x transposed: [B][D][N]
__device__ __nv_bfloat16 g_combh[BB * 1024 * NTOK]; // hi(comb) [B][k][n]
__device__ __nv_bfloat16 g_combl[BB * 1024 * NTOK]; // lo(comb) [B][k][n]
__device__ __nv_bfloat16 g_Wh[DD * 1024];           // hi(Wout) [j][k]
__device__ __nv_bfloat16 g_Wl[DD * 1024];           // lo(Wout) [j][k]
__device__ float g_pooled[BB * DD];
__device__ float g_gamma[BB * DD];

// ---------------- small asm helpers ------------------------------------------
__device__ __forceinline__ uint32_t smem_u32(const void* p) {
    uint32_t a;
    asm("{.reg .u64 t; cvta.to.shared.u64 t, %1; cvt.u32.u64 %0, t;}" : "=r"(a) : "l"(p));
    return a;
}
__device__ __forceinline__ void ldmx4t(uint32_t* r, uint32_t a) {
    asm volatile("ldmatrix.sync.aligned.m8n8.x4.trans.shared.b16 {%0,%1,%2,%3}, [%4];"
                 : "=r"(r[0]), "=r"(r[1]), "=r"(r[2]), "=r"(r[3]) : "r"(a));
}
__device__ __forceinline__ void ldmx2(uint32_t* r, uint32_t a) {
    asm volatile("ldmatrix.sync.aligned.m8n8.x2.shared.b16 {%0,%1}, [%2];"
                 : "=r"(r[0]), "=r"(r[1]) : "r"(a));
}
__device__ __forceinline__ void mma16816(float* c, const uint32_t* a, const uint32_t* b) {
    asm volatile("mma.sync.aligned.m16n8k16.row.col.f32.bf16.bf16.f32 "
                 "{%0,%1,%2,%3}, {%4,%5,%6,%7}, {%8,%9}, {%0,%1,%2,%3};"
                 : "+f"(c[0]), "+f"(c[1]), "+f"(c[2]), "+f"(c[3])
                 : "r"(a[0]), "r"(a[1]), "r"(a[2]), "r"(a[3]), "r"(b[0]), "r"(b[1]));
}
__device__ __forceinline__ void cp16(uint32_t sdst, const void* gsrc) {
    asm volatile("cp.async.ca.shared.global [%0], [%1], 16;" :: "r"(sdst), "l"(gsrc));
}
__device__ __forceinline__ void cp_commit() {
    asm volatile("cp.async.commit_group;");
}
__device__ __forceinline__ void split_bf16(float v, __nv_bfloat16& h, __nv_bfloat16& l) {
    h = __float2bfloat16(v);
    l = __float2bfloat16(v - __bfloat162float(h));
}

// exact logistic reaction on one complex value (r,m) for time with exp term ex
__device__ __forceinline__ void react1(float& r, float& m,
                                       float a2, float b2, bool tiny,
                                       float tt, float ex) {
    float q = r * r + m * m;
    float qn;
    if (tiny) qn = q / (1.f + b2 * q * tt);
    else { float den = fmaxf(b2 * q + (a2 - b2 * q) * ex, 1e-8f); qn = a2 * q / den; }
    qn = fmaxf(qn, 0.f);
    float sc = sqrtf(qn / fmaxf(q, 1e-8f));
    r *= sc; m *= sc;
}

// ---------------- 8-point FFT (SGN=-1 fwd, +1 inv; unnormalized) -------------
template<int SGN>
__device__ __forceinline__ void fft8(float* xr, float* xi) {
    const float s = (float)SGN;
    float a0r = xr[0] + xr[4], a0i = xi[0] + xi[4];
    float a1r = xr[0] - xr[4], a1i = xi[0] - xi[4];
    float b0r = xr[2] + xr[6], b0i = xi[2] + xi[6];
    float b1r = xr[2] - xr[6], b1i = xi[2] - xi[6];
    float c0r = xr[1] + xr[5], c0i = xi[1] + xi[5];
    float c1r = xr[1] - xr[5], c1i = xi[1] - xi[5];
    float d0r = xr[3] + xr[7], d0i = xi[3] + xi[7];
    float d1r = xr[3] - xr[7], d1i = xi[3] - xi[7];
    float e0r = a0r + b0r, e0i = a0i + b0i;
    float e2r = a0r - b0r, e2i = a0i - b0i;
    float wbr = -s * b1i,  wbi =  s * b1r;
    float e1r = a1r + wbr, e1i = a1i + wbi;
    float e3r = a1r - wbr, e3i = a1i - wbi;
    float o0r = c0r + d0r, o0i = c0i + d0i;
    float o2r = c0r - d0r, o2i = c0i - d0i;
    float wdr = -s * d1i,  wdi =  s * d1r;
    float o1r = c1r + wdr, o1i = c1i + wdi;
    float o3r = c1r - wdr, o3i = c1i - wdi;
    const float r2 = 0.70710678118654752440f;
    float t1r =  r2 * (o1r - s * o1i), t1i = r2 * (o1i + s * o1r);
    float t2r = -s * o2i,              t2i = s * o2r;
    float t3r = -r2 * (o3r + s * o3i), t3i = r2 * (s * o3r - o3i);
    xr[0] = e0r + o0r; xi[0] = e0i + o0i;
    xr[4] = e0r - o0r; xi[4] = e0i - o0i;
    xr[1] = e1r + t1r; xi[1] = e1i + t1i;
    xr[5] = e1r - t1r; xi[5] = e1i - t1i;
    xr[2] = e2r + t2r; xi[2] = e2i + t2i;
    xr[6] = e2r - t2r; xi[6] = e2i - t2i;
    xr[3] = e3r + t3r; xi[3] = e3i + t3i;
    xr[7] = e3r - t3r; xi[7] = e3i - t3i;
}

// One 64-pt line: [optional reaction] -> fwd FFT -> x phase1d(k) (1/64 folded)
// -> inv FFT -> [optional reaction] -> store.
// Complex state interleaved as float2 in smem: one LDS.64/STS.64 per element.
// Bank-pair analysis (8B units, 16 pairs, 2-phase minimum for 64-bit):
// all six smem rounds hit each pair exactly twice -> conflict-optimal.
// 8 threads (t=0..7) per line; layout in/out: elem n at slot (t + 8j).
// Transposes through smem with XOR-swizzled slots: slot(a,b) = 8a + (a^b).
template<bool RLOAD, bool RSTORE>
__device__ __forceinline__ void do_line(
    float2* sc, int base, int stride, int t,
    const float* twr, const float* twi, const float* phr, const float* phi,
    float a2, float b2, bool tiny,
    float ttL, float exL, float ttS, float exS)
{
    float xr[8], xi[8];
#pragma unroll
    for (int j = 0; j < 8; j++) {
        int p = base + (t + 8 * j) * stride;
        float2 v = sc[p];
        xr[j] = v.x; xi[j] = v.y;
        if (RLOAD) react1(xr[j], xi[j], a2, b2, tiny, ttL, exL);
    }
    fft8<-1>(xr, xi);                       // over n2 -> reg index k1
#pragma unroll
    for (int j = 1; j < 8; j++) {           // * W64^{t*k1}
        float r = xr[j] * twr[j] - xi[j] * twi[j];
        float m = xr[j] * twi[j] + xi[j] * twr[j];
        xr[j] = r; xi[j] = m;
    }
    __syncwarp();
#pragma unroll
    for (int j = 0; j < 8; j++) { int p = base + (8 * t + (t ^ j)) * stride; sc[p] = make_float2(xr[j], xi[j]); }
    __syncwarp();
#pragma unroll
    for (int j = 0; j < 8; j++) { int p = base + (8 * j + (t ^ j)) * stride; float2 v = sc[p]; xr[j] = v.x; xi[j] = v.y; }
    fft8<-1>(xr, xi);                       // over n1 -> reg index k2; X[t + 8*k2]
#pragma unroll
    for (int j = 0; j < 8; j++) {           // * phase[k] * (1/64)
        int k = t + 8 * j;
        float pr = phr[k], pi = phi[k];
        float r = xr[j] * pr - xi[j] * pi;
        float m = xr[j] * pi + xi[j] * pr;
        xr[j] = r; xi[j] = m;
    }
    fft8<1>(xr, xi);                        // inverse over k2 -> reg index n1
#pragma unroll
    for (int j = 1; j < 8; j++) {           // * conj(W64^{t*n1})
        float r = xr[j] * twr[j] + xi[j] * twi[j];
        float m = xi[j] * twr[j] - xr[j] * twi[j];
        xr[j] = r; xi[j] = m;
    }
    __syncwarp();
#pragma unroll
    for (int j = 0; j < 8; j++) { int p = base + (8 * t + (t ^ j)) * stride; sc[p] = make_float2(xr[j], xi[j]); }
    __syncwarp();
#pragma unroll
    for (int j = 0; j < 8; j++) { int p = base + (8 * j + (t ^ j)) * stride; float2 v = sc[p]; xr[j] = v.x; xi[j] = v.y; }
    fft8<1>(xr, xi);                        // inverse over k1 -> reg index n2
#pragma unroll
    for (int j = 0; j < 8; j++) {
        if (RSTORE) react1(xr[j], xi[j], a2, b2, tiny, ttS, exS);
        int p = base + (t + 8 * j) * stride;
        sc[p] = make_float2(xr[j], xi[j]);
    }
}

// ---------------- kernels ----------------------------------------------------

__global__ void k_transpose_x(const float* __restrict__ x) {
    __shared__ float tile[32][33];
    int b = blockIdx.z;
    int d0 = blockIdx.x * 32, n0 = blockIdx.y * 32;
    int tx = threadIdx.x, ty = threadIdx.y;
#pragma unroll
    for (int i = 0; i < 32; i += 8)
        tile[ty + i][tx] = x[((size_t)b * NTOK + n0 + ty + i) * DD + d0 + tx];
    __syncthreads();
#pragma unroll
    for (int i = 0; i < 32; i += 8)
        g_xt[((size_t)b * DD + d0 + ty + i) * NTOK + n0 + tx] = tile[tx][ty + i];
}

// Wout is [j=512][k=1024] row-major already: elementwise hi/lo bf16 split.
__global__ void k_prep_w(const float* __restrict__ Wout) {
    int idx = blockIdx.x * 256 + threadIdx.x;
    float v = Wout[idx];
    __nv_bfloat16 h, l;
    split_bf16(v, h, l);
    g_Wh[idx] = h; g_Wl[idx] = l;
}

__global__ void k_pooled() {
    int g = blockIdx.x * 8 + (threadIdx.x >> 5);   // channel id b*512+d
    int lane = threadIdx.x & 31;
    const float4* p = (const float4*)(g_xt + (size_t)g * NTOK);
    float s = 0.f;
    for (int i = lane; i < NTOK / 4; i += 32) {
        float4 v = p[i];
        s += (v.x + v.y) + (v.z + v.w);
    }
#pragma unroll
    for (int o = 16; o; o >>= 1) s += __shfl_down_sync(0xffffffffu, s, o);
    if (!lane) g_pooled[g] = s * (1.0f / NTOK);
}

__global__ void k_gamma(const float* __restrict__ Wg, const float* __restrict__ bg,
                        const float* __restrict__ log_base) {
    int g = blockIdx.x * 8 + (threadIdx.x >> 5);   // b*512+d
    int b = g >> 9, d = g & 511;
    int lane = threadIdx.x & 31;
    // float4-vectorized dot: 4x MLP on this latency-bound reduction
    // (measured r8: 12us, DRAM 1.1%, issue 14.4% -> LDG-latency bound)
    const float4* pw = (const float4*)(Wg + (size_t)d * DD);
    const float4* pp = (const float4*)(g_pooled + (size_t)b * DD);
    float s = 0.f;
    for (int k = lane; k < DD / 4; k += 32) {
        float4 w = pw[k], v = pp[k];
        s += w.x * v.x + w.y * v.y + w.z * v.z + w.w * v.w;
    }
#pragma unroll
    for (int o = 16; o; o >>= 1) s += __shfl_down_sync(0xffffffffu, s, o);
    if (!lane) {
        float z = s + bg[d] + log_base[d];
        float sp = (z > 20.f) ? z : log1pf(expf(z));
        g_gamma[g] = fminf(sp, 0.35f);
    }
}

__global__ void __launch_bounds__(256) k_main(const float* __restrict__ alpha_raw,
                                              const float* __restrict__ beta_raw,
                                              const int* __restrict__ k_steps_p) {
    __shared__ float2 sc[HH * LDS_];    // interleaved complex, 34.8KB
    __shared__ float phr[64], phi[64];

    int bd  = blockIdx.x;
    int d   = bd & 511;
    int tid = threadIdx.x;
    int t   = tid & 7;
    int grp = tid >> 3;            // 0..31

    // x-pass line assignment bijection: spreads each warp's 4 lines by 2 to
    // decorrelate row-base bank pairs (see do_line bank note).
    int xline0 = 2 * (grp & 3) + ((grp >> 2) & 1) + ((grp >> 3) << 3);

    int ks = *k_steps_p; if (ks < 1) ks = 1;
    float dt = 1.0f / (float)ks;

    float gamma = g_gamma[bd];
    float alpha = 0.25f * tanhf(alpha_raw[d]);
    float brw = beta_raw[d];
    float beta = ((brw > 20.f) ? brw : log1pf(expf(brw))) + 1e-4f;

    if (tid < 64) {
        float e = 2.0f * __cosf((float)tid * (TWO_PI / 64.0f)) - 2.0f;
        float arg = dt * gamma * e;
        float sn, cs;
        __sincosf(arg, &sn, &cs);
        phr[tid] = cs * (1.0f / 64.0f);   // 1/64 per dimension -> 1/4096 total
        phi[tid] = sn * (1.0f / 64.0f);
    }

    float twr[8], twi[8];
#pragma unroll
    for (int j = 0; j < 8; j++) {
        float ang = (float)(t * j) * (TWO_PI / 64.0f);
        float sn, cs;
        __sincosf(ang, &sn, &cs);
        twr[j] = cs; twi[j] = -sn;        // forward W64^{t*j}; inverse = conj
    }

    // vectorized fill: LDG.128 + 2x STS.128 per 4 elements
    // ((68y+xx)*8 with xx % 4 == 0 -> 16B-aligned float4 smem stores)
    const float4* src4 = (const float4*)(g_xt + (size_t)bd * NTOK);
    for (int i4 = tid; i4 < NTOK / 4; i4 += 256) {
        float4 v = src4[i4];
        int n = i4 * 4;
        float4* dst = (float4*)&sc[(n >> 6) * LDS_ + (n & 63)];
        dst[0] = make_float4(v.x, 0.f, v.y, 0.f);
        dst[1] = make_float4(v.z, 0.f, v.w, 0.f);
    }
    __syncthreads();

    // reaction time constants. Strang splitting R(th) D [R(tf) D]^(ks-1) R(th)
    // with exact-flow merge of interior half steps; reactions fused into the
    // FFT passes (x-pass on load; last y-pass on store).
    float a2 = 2.f * alpha, b2 = 2.f * beta;
    bool tiny = fabsf(a2) < 1e-6f;
    float th = 0.5f * dt, tf = dt;
    float exh = __expf(-a2 * th), exf = __expf(-a2 * tf);

    for (int step = 0; step < ks; ++step) {
        float ttL = (step == 0) ? th : tf;
        float exL = (step == 0) ? exh : exf;
        bool last = (step == ks - 1);
        // ---- x-direction (rows): reaction on load + diffusion
#pragma unroll
        for (int rep = 0; rep < 2; rep++) {
            int line = xline0 + 32 * rep;
            do_line<true, false>(sc, line * LDS_, 1, t, twr, twi, phr, phi,
                                 a2, b2, tiny, ttL, exL, 0.f, 0.f);
        }
        __syncthreads();
        // ---- y-direction (columns); trailing half reaction on last step
        if (last) {
#pragma unroll
            for (int rep = 0; rep < 2; rep++) {
                int line = grp + 32 * rep;
                do_line<false, true>(sc, line, LDS_, t, twr, twi, phr, phi,
                                     a2, b2, tiny, 0.f, 0.f, th, exh);
            }
        } else {
#pragma unroll
            for (int rep = 0; rep < 2; rep++) {
                int line = grp + 32 * rep;
                do_line<false, false>(sc, line, LDS_, t, twr, twi, phr, phi,
                                      a2, b2, tiny, 0.f, 0.f, 0.f, 0.f);
            }
        }
        __syncthreads();
    }

    // epilogue: hi/lo bf16 split, [k][n] layout; two points packed per
    // bf16x2 word -> STG.32 (half the store instructions of STG.16 path)
    int b = bd >> 9;
    size_t baser = ((size_t)b * 1024 + d) * NTOK;
    size_t basei = ((size_t)b * 1024 + 512 + d) * NTOK;
    for (int i2 = tid; i2 < NTOK / 2; i2 += 256) {
        int n = i2 * 2;
        int idx = (n >> 6) * LDS_ + (n & 63);
        float2 v0 = sc[idx], v1 = sc[idx + 1];
        __nv_bfloat16 h0, l0, h1, l1;
        __nv_bfloat162 p;
        split_bf16(v0.x, h0, l0); split_bf16(v1.x, h1, l1);
        p.x = h0; p.y = h1; *(__nv_bfloat162*)(&g_combh[baser + n]) = p;
        p.x = l0; p.y = l1; *(__nv_bfloat162*)(&g_combl[baser + n]) = p;
        split_bf16(v0.y, h0, l0); split_bf16(v1.y, h1, l1);
        p.x = h0; p.y = h1; *(__nv_bfloat162*)(&g_combh[basei + n]) = p;
        p.x = l0; p.y = l1; *(__nv_bfloat162*)(&g_combl[basei + n]) = p;
    }
}

// out[b,n,j] = sum_k comb[k,n]*W[j,k] + x[b,n,j]*Dp[j]
// bf16 tensor-core GEMM, hi/lo 3-term split, 2-stage cp.async pipeline.
// A consumed directly from comb's [k][n] layout via ldmatrix.trans.
// Block: 128(n) x 128(j), K-step 16; 8 warps = 2(mw) x 4(jw), warp tile 64x32.
#define AROWW  68                         // A row stride in words (272B)
#define ABUFW  (16 * AROWW)               // 1088 words
#define ASTGW  (2 * ABUFW)                // 2176 words (8704B)
#define ROWW   12                         // B row stride in words (48B)
#define BUFW   (128 * ROWW)               // 1536 words
#define STGW   (2 * BUFW)                 // 3072 words (12288B)

__global__ void __launch_bounds__(256, 2) k_gemm(const float* __restrict__ x,
                                                 const float* __restrict__ Dp,
                                                 float* __restrict__ out) {
    __shared__ uint32_t Ash[2 * ASTGW];   // ~17.4KB
    __shared__ uint32_t Bsh[2 * STGW];    // 24KB  (total ~41.4KB)

    int b  = blockIdx.z;
    int j0 = blockIdx.x * 128;            // j fastest -> A-tile L2 reuse across 4 CTAs
    int m0 = blockIdx.y * 128;
    int tid = threadIdx.x;
    int warp = tid >> 5, lane = tid & 31;
    int mw = warp & 1, jw = warp >> 1;

    float acc[4][4][4];
#pragma unroll
    for (int ms = 0; ms < 4; ms++)
#pragma unroll
        for (int js = 0; js < 4; js++)
#pragma unroll
            for (int e = 0; e < 4; e++) acc[ms][js][e] = 0.f;

    uint32_t aBase = smem_u32(Ash);
    uint32_t bBase = smem_u32(Bsh);
    // A ldmatrix.trans per-lane address (frag order: {m0-7,k0-7},{m8-15,k0-7},
    // {m0-7,k8-15},{m8-15,k8-15}): lane group g=lane>>3 -> matrix g;
    // k-row = (g>>1)*8 + (lane&7); n-offset = (g&1)*8 elems.
    int matA = lane >> 3, rinA = lane & 7;
    uint32_t aAddr0 = aBase +
        (uint32_t)((((matA >> 1) * 8 + rinA) * AROWW + (matA & 1) * 4 + mw * 32) * 4);
    int l16 = lane & 15;
    int matB = l16 >> 3, rinB = l16 & 7;
    uint32_t bAddr0 = bBase + (uint32_t)(((jw * 32 + rinB) * ROWW + matB * 4) * 4);

    auto load_stage = [&](int st, int k0) {
        // A: 2 bufs x 16 k-rows x 16 chunks(16B) = 512 cp16
#pragma unroll
        for (int u = 0; u < 2; u++) {
            int idx = tid + 256 * u;
            int buf = idx >> 8, r = (idx >> 4) & 15, c = idx & 15;
            const __nv_bfloat16* As = buf ? g_combl : g_combh;
            const void* g = As + ((size_t)(b * 1024 + k0 + r)) * NTOK + m0 + c * 8;
            cp16(aBase + (uint32_t)((st * ASTGW + buf * ABUFW + r * AROWW + c * 4) * 4), g);
        }
        // B: 2 bufs x 128 j-rows x 2 chunks = 512 cp16
#pragma unroll
        for (int u = 0; u < 2; u++) {
            int idx = tid + 256 * u;
            int buf = idx >> 8, r = (idx >> 1) & 127, c = idx & 1;
            const __nv_bfloat16* Ws = buf ? g_Wl : g_Wh;
            const void* g = Ws + (size_t)(j0 + r) * 1024 + k0 + c * 8;
            cp16(bBase + (uint32_t)((st * STGW + buf * BUFW + r * ROWW + c * 4) * 4), g);
        }
        cp_commit();
    };

    load_stage(0, 0);

    for (int it = 0; it < 64; ++it) {
        int cur = it & 1;
        if (it + 1 < 64) {
            load_stage(cur ^ 1, (it + 1) * 16);
            asm volatile("cp.async.wait_group 1;" ::: "memory");
        } else {
            asm volatile("cp.async.wait_group 0;" ::: "memory");
        }
        __syncthreads();

        uint32_t aS = aAddr0 + (uint32_t)(cur * ASTGW * 4);
        uint32_t bS = bAddr0 + (uint32_t)(cur * STGW * 4);
        uint32_t bh[4][2], bl[4][2];
#pragma unroll
        for (int js = 0; js < 4; js++) {
            ldmx2(bh[js], bS + js * 8 * ROWW * 4);
            ldmx2(bl[js], bS + js * 8 * ROWW * 4 + BUFW * 4);
        }
#pragma unroll
        for (int ms = 0; ms < 4; ms++) {
            uint32_t ah[4], al[4];
            ldmx4t(ah, aS + ms * 32);                 // ms*16 n-elems = 8 words
            ldmx4t(al, aS + ms * 32 + ABUFW * 4);
#pragma unroll
            for (int js = 0; js < 4; js++) {
                mma16816(acc[ms][js], ah, bh[js]);
                mma16816(acc[ms][js], ah, bl[js]);
                mma16816(acc[ms][js], al, bh[js]);
            }
        }
        __syncthreads();
    }

    // epilogue: D frag: d0,d1 = (row l>>2, col (l&3)*2, +1); d2,d3 = row+8
    int rg = lane >> 2, cp = (lane & 3) * 2;
#pragma unroll
    for (int ms = 0; ms < 4; ms++) {
#pragma unroll
        for (int js = 0; js < 4; js++) {
            int j = j0 + jw * 32 + js * 8 + cp;
            float2 dpv = *(const float2*)(Dp + j);
            int n = m0 + mw * 64 + ms * 16 + rg;
            size_t idx0 = ((size_t)b * NTOK + n) * DD + j;
            float2 xv0 = *(const float2*)(x + idx0);
            float2 o0;
            o0.x = acc[ms][js][0] + xv0.x * dpv.x;
            o0.y = acc[ms][js][1] + xv0.y * dpv.y;
            *(float2*)(out + idx0) = o0;
            size_t idx1 = idx0 + 8 * DD;
            float2 xv1 = *(const float2*)(x + idx1);
            float2 o1;
            o1.x = acc[ms][js][2] + xv1.x * dpv.x;
            o1.y = acc[ms][js][3] + xv1.y * dpv.y;
            *(float2*)(out + idx1) = o1;
        }
    }
}

// ---------------- launch ------------------------------------------------------
// Order chosen so k_main is the 4th kernel launch: the ncu capture window
// (-s 5 -c 1, with 2 harness launches ahead of ours) lands on launch #4.
extern "C" void kernel_launch(void* const* d_in, const int* in_sizes, int n_in,
                              void* d_out, int out_size) {
    const float* x         = (const float*)d_in[0];
    const float* Wg        = (const float*)d_in[1];
    const float* bg        = (const float*)d_in[2];
    const float* log_base  = (const float*)d_in[3];
    const float* alpha_raw = (const float*)d_in[4];
    const float* beta_raw  = (const float*)d_in[5];
    const float* Wout      = (const float*)d_in[6];
    const float* Dparam    = (const float*)d_in[7];
    const int*   k_steps   = (const int*)d_in[8];
    float* out = (float*)d_out;

    k_transpose_x<<<dim3(DD / 32, NTOK / 32, BB), dim3(32, 8)>>>(x);
    k_pooled<<<BB * DD / 8, 256>>>();
    k_gamma<<<BB * DD / 8, 256>>>(Wg, bg, log_base);
    k_main<<<BB * DD, 256>>>(alpha_raw, beta_raw, k_steps);
    k_prep_w<<<(DD * 1024) / 256, 256>>>(Wout);
    k_gemm<<<dim3(DD / 128, NTOK / 128, BB), 256>>>(x, Dparam, out);
}